// round 15
// baseline (speedup 1.0000x reference)
#include <cuda_runtime.h>
#include <cuda_fp16.h>
#include <math.h>
#include <stdint.h>

#define Bq 2
#define Sq 2048
#define Dq 512
#define Hq 8

#define SDc  ((long)Sq * Dq)
#define SSc  ((long)Sq * Sq)
#define DDc  ((long)Dq * Dq)

#define X_PLANE    ((long)Bq * Sq * Dq)
#define W_PLANE    ((long)Hq * Dq * Dq)
#define QK_PLANE   ((long)Bq * Hq * Sq * Dq)
#define Z_PLANE    QK_PLANE

__device__ __align__(256) float g_attn[(long)Bq * Hq * Sq * Sq];
__device__ __align__(256) __half g_x  [3 * X_PLANE];
__device__ __align__(256) __half g_w  [3 * W_PLANE];
__device__ __align__(256) __half g_wzt[2 * W_PLANE];
__device__ __align__(256) __half g_qk [2 * QK_PLANE];
__device__ __align__(256) __half g_vts[QK_PLANE];
__device__ __align__(256) __half g_zs [Z_PLANE];
__device__ __align__(256) float g_m [(long)Bq * Hq * Sq];
__device__ __align__(256) float g_ti[(long)Bq * Hq * Sq];

struct Off { int dv; long s1; int md; long s2; };

__device__ __forceinline__ uint32_t smem_u32(const void* p) {
    uint32_t a;
    asm("{ .reg .u64 t; cvta.to.shared.u64 t, %1; cvt.u32.u64 %0, t; }" : "=r"(a) : "l"(p));
    return a;
}
__device__ __forceinline__ void cpasync16(uint32_t dst, const void* src) {
    asm volatile("cp.async.cg.shared.global [%0], [%1], 16;" :: "r"(dst), "l"(src) : "memory");
}
#define CP_COMMIT() asm volatile("cp.async.commit_group;" ::: "memory")
#define CP_WAIT1()  asm volatile("cp.async.wait_group 1;" ::: "memory")
#define CP_WAIT0()  asm volatile("cp.async.wait_group 0;" ::: "memory")

#define LDSM4(r, a) \
    asm volatile("ldmatrix.sync.aligned.m8n8.x4.shared.b16 {%0,%1,%2,%3}, [%4];" \
        : "=r"((r)[0]), "=r"((r)[1]), "=r"((r)[2]), "=r"((r)[3]) : "r"(a))

#define MMAF(c, a, b0, b1) \
    asm volatile("mma.sync.aligned.m16n8k16.row.col.f32.f16.f16.f32 " \
        "{%0,%1,%2,%3},{%4,%5,%6,%7},{%8,%9},{%0,%1,%2,%3};" \
        : "+f"((c)[0]), "+f"((c)[1]), "+f"((c)[2]), "+f"((c)[3]) \
        : "r"((a)[0]), "r"((a)[1]), "r"((a)[2]), "r"((a)[3]), "r"(b0), "r"(b1))

#define MMAH(c, a, b0, b1) \
    asm volatile("mma.sync.aligned.m16n8k16.row.col.f16.f16.f16.f16 " \
        "{%0,%1},{%2,%3,%4,%5},{%6,%7},{%0,%1};" \
        : "+r"((c)[0]), "+r"((c)[1]) \
        : "r"((a)[0]), "r"((a)[1]), "r"((a)[2]), "r"((a)[3]), "r"(b0), "r"(b1))

__device__ __forceinline__ void split1(float x, __half& h, __half& l) {
    h = __float2half_rn(x);
    l = __float2half_rn(x - __half2float(h));
}
__device__ __forceinline__ uint32_t pack2(__half a, __half b) {
    __half2 t; t.x = a; t.y = b;
    return *reinterpret_cast<uint32_t*>(&t);
}
__device__ __forceinline__ void sts8(uint32_t addr, uint32_t x, uint32_t y) {
    asm volatile("st.shared.v2.b32 [%0], {%1,%2};" :: "r"(addr), "r"(x), "r"(y) : "memory");
}

#define STAGE_B  16384
#define STAGE_SZ 32768
#define NSTAGE   3
#define SMEM_SZ  (NSTAGE * STAGE_SZ)

// ---------------------------------------------------------------------------
// fp16 HMMA TN GEMM — 256 threads (8 warps, warp tile 64x32), 2 CTAs/SM.
// PMASK: 0 = hi-pass only; 1 adds Ah.Bl f16acc.
// mode 0: fp32 out (+bias). mode 1: fp16 hi out. mode 2: fp16 hi transposed.
// ---------------------------------------------------------------------------
template <int PMASK>
__global__ void __launch_bounds__(256, 2)
gemm_mma(const __half* __restrict__ A, long aplane,
         const __half* __restrict__ B, long bplane,
         void* Cv,
         int K, int lda, int ldb, int ldc,
         Off oa, Off ob, Off oc,
         float alpha, const float* __restrict__ bias, int mode)
{
    constexpr bool needBlo = (PMASK & 1) != 0;

    extern __shared__ char smem[];
    const uint32_t sm = smem_u32(smem);
    const int tid = threadIdx.x, wid = tid >> 5, lane = tid & 31;
    const int z = blockIdx.z;

    const __half* Ahp = A + (long)(z / oa.dv) * oa.s1 + (long)(z % oa.md) * oa.s2;
    const __half* Bhp = B + (long)(z / ob.dv) * ob.s1 + (long)(z % ob.md) * ob.s2;
    const long coff = (long)(z / oc.dv) * oc.s1 + (long)(z % oc.md) * oc.s2;

    const long row0 = (long)blockIdx.y * 128;
    const long col0 = (long)blockIdx.x * 128;

    // loader: 2 threads/row; lpl=0 -> hi chunks 0-3, lpl=1 -> lo chunks 4-7
    const int lrow = tid >> 1;
    const int lpl  = tid & 1;
    const __half* Asrc = Ahp + (row0 + lrow) * lda;                       // hi only
    const __half* Bsrc = (lpl ? Bhp + bplane : Bhp) + (col0 + lrow) * ldb;
    const bool doA = (lpl == 0);
    const bool doB = (lpl == 0) || needBlo;
    uint32_t soff[4];
    #pragma unroll
    for (int j = 0; j < 4; ++j) {
        const int c = lpl * 4 + j;
        soff[j] = lrow * 128 + ((c ^ (lrow & 7)) << 4);
    }

    // compute mapping: warp grid 2(m) x 4(n); warp tile 64x32
    const int wm = wid & 1, wn = wid >> 1;
    const int g = lane >> 3, r8 = lane & 7;
    const int a_roff = ((g & 1) << 3) + r8;
    const int a_kh   = g >> 1;
    const int b_roff = ((g >> 1) << 3) + r8;
    const int b_kh   = g & 1;

    uint32_t a_row[4], a_rx[4];
    #pragma unroll
    for (int mt = 0; mt < 4; ++mt) {
        const int row = wm * 64 + mt * 16 + a_roff;
        a_row[mt] = row * 128;
        a_rx[mt] = row & 7;
    }
    uint32_t b_row[2], b_rx[2];
    #pragma unroll
    for (int np = 0; np < 2; ++np) {
        const int row = wn * 32 + np * 16 + b_roff;
        b_row[np] = row * 128;
        b_rx[np] = row & 7;
    }

    float acc[4][4][4];
    uint32_t acch[4][4][2];
    #pragma unroll
    for (int i = 0; i < 4; ++i)
        #pragma unroll
        for (int j = 0; j < 4; ++j) {
            #pragma unroll
            for (int q = 0; q < 4; ++q) acc[i][j][q] = 0.0f;
            acch[i][j][0] = 0u; acch[i][j][1] = 0u;
        }

    const int nst = K / 32;

    #pragma unroll
    for (int p = 0; p < 2; ++p) {
        if (p < nst) {
            const uint32_t tb = sm + p * STAGE_SZ;
            const long k0 = (long)p * 32;
            #pragma unroll
            for (int j = 0; j < 4; ++j) {
                if (doA) cpasync16(tb + soff[j], Asrc + k0 + j * 8);
                if (doB) cpasync16(tb + STAGE_B + soff[j], Bsrc + k0 + j * 8);
            }
        }
        CP_COMMIT();
    }

    int stg = 0;
    for (int s = 0; s < nst; ++s) {
        if (s + 1 < nst) CP_WAIT1(); else CP_WAIT0();
        __syncthreads();

        const uint32_t tb = sm + stg * STAGE_SZ;
        const uint32_t tba = tb, tbb = tb + STAGE_B;

        #pragma unroll
        for (int ks = 0; ks < 2; ++ks) {
            const int ca = ks * 2 + a_kh;
            const int cb = ks * 2 + b_kh;

            uint32_t Ahr[4][4], Bhr[2][4];
            #pragma unroll
            for (int mt = 0; mt < 4; ++mt)
                LDSM4(Ahr[mt], tba + a_row[mt] + ((ca ^ a_rx[mt]) << 4));
            #pragma unroll
            for (int np = 0; np < 2; ++np)
                LDSM4(Bhr[np], tbb + b_row[np] + ((cb ^ b_rx[np]) << 4));
            #pragma unroll
            for (int mt = 0; mt < 4; ++mt)
                #pragma unroll
                for (int nt = 0; nt < 4; ++nt) {
                    const int np = nt >> 1, s2 = (nt & 1) * 2;
                    MMAF(acc[mt][nt], Ahr[mt], Bhr[np][s2], Bhr[np][s2 + 1]);
                }

            if (needBlo) {
                uint32_t Blr[2][4];
                #pragma unroll
                for (int np = 0; np < 2; ++np)
                    LDSM4(Blr[np], tbb + b_row[np] + (((cb + 4) ^ b_rx[np]) << 4));
                #pragma unroll
                for (int mt = 0; mt < 4; ++mt)
                    #pragma unroll
                    for (int nt = 0; nt < 4; ++nt) {
                        const int np = nt >> 1, s2 = (nt & 1) * 2;
                        MMAH(acch[mt][nt], Ahr[mt], Blr[np][s2], Blr[np][s2 + 1]);
                    }
            }
        }

        if (s + 2 < nst) {
            int ps = stg + 2; if (ps >= NSTAGE) ps -= NSTAGE;
            const uint32_t pb = sm + ps * STAGE_SZ;
            const long k0 = (long)(s + 2) * 32;
            #pragma unroll
            for (int j = 0; j < 4; ++j) {
                if (doA) cpasync16(pb + soff[j], Asrc + k0 + j * 8);
                if (doB) cpasync16(pb + STAGE_B + soff[j], Bsrc + k0 + j * 8);
            }
        }
        CP_COMMIT();

        if (++stg == NSTAGE) stg = 0;
    }

    const int r_in = lane >> 2, c_in = (lane & 3) * 2;
    #pragma unroll
    for (int mt = 0; mt < 4; ++mt) {
        #pragma unroll
        for (int half = 0; half < 2; ++half) {
            const long row = row0 + wm * 64 + mt * 16 + half * 8 + r_in;
            #pragma unroll
            for (int nt = 0; nt < 4; ++nt) {
                const int colg = (int)col0 + wn * 32 + nt * 8 + c_in;
                float v0 = acc[mt][nt][half * 2 + 0];
                float v1 = acc[mt][nt][half * 2 + 1];
                if (PMASK) {
                    float2 cf = __half22float2(*reinterpret_cast<__half2*>(&acch[mt][nt][half]));
                    v0 += cf.x;
                    v1 += cf.y;
                }
                v0 *= alpha;
                v1 *= alpha;
                if (mode == 0) {
                    if (bias) { v0 += bias[colg]; v1 += bias[colg + 1]; }
                    *(float2*)((float*)Cv + coff + row * ldc + colg) = make_float2(v0, v1);
                } else if (mode == 1) {
                    uint32_t hw = pack2(__float2half_rn(v0), __float2half_rn(v1));
                    *(uint32_t*)((__half*)Cv + coff + row * ldc + colg) = hw;
                } else {
                    __half* Ch = (__half*)Cv + coff;
                    Ch[(long)colg * ldc + row] = __float2half_rn(v0);
                    Ch[(long)(colg + 1) * ldc + row] = __float2half_rn(v1);
                }
            }
        }
    }
}

// ---------------------------------------------------------------------------
// PV kernel (unchanged from R14)
// ---------------------------------------------------------------------------
#define PV_BB   8192
#define PV_STG  40960
#define PV_SMEM (3 * PV_STG)

__global__ void __launch_bounds__(512, 1)
pv_kernel(const float* __restrict__ S, const __half* __restrict__ V,
          __half* __restrict__ Z)
{
    extern __shared__ char smem[];
    const uint32_t sm = smem_u32(smem);
    const int tid = threadIdx.x, wid = tid >> 5, lane = tid & 31;
    const int z = blockIdx.z;
    const long row0 = (long)blockIdx.y * 64;
    const long col0 = (long)blockIdx.x * 256;

    const int ar  = tid >> 3;
    const int seg = tid & 7;
    const long rowg = row0 + ar;
    const float* Sp = S + (long)z * SSc + rowg * Sq + seg * 4;
    const float m  = g_m [(long)z * Sq + rowg];
    const float ti = g_ti[(long)z * Sq + rowg];
    const uint32_t a_hi = ar * 128 + ((((seg >> 1) + 0) ^ (ar & 7)) << 4) + (seg & 1) * 8;
    const uint32_t a_lo = ar * 128 + ((((seg >> 1) + 4) ^ (ar & 7)) << 4) + (seg & 1) * 8;

    const int br = tid >> 1;
    const int bc = (tid & 1) * 2;
    const __half* Vp = V + (long)z * SDc + (col0 + br) * Sq;
    const uint32_t b_s0 = br * 128 + (((bc + 0) ^ (br & 7)) << 4);
    const uint32_t b_s1 = br * 128 + (((bc + 1) ^ (br & 7)) << 4);
    const int bko = bc * 8;

    const int wm = wid & 3, wn = wid >> 2;
    const int g = lane >> 3, r8 = lane & 7;
    const int a_roff = ((g & 1) << 3) + r8;
    const int a_kh   = g >> 1;
    const int b_roff = ((g >> 1) << 3) + r8;
    const int b_kh   = g & 1;

    const int arc = wm * 16 + a_roff;
    const uint32_t a_rowb = arc * 128;
    const uint32_t a_rx = arc & 7;
    uint32_t b_rowb[4], b_rx[4];
    #pragma unroll
    for (int np = 0; np < 4; ++np) {
        const int row = wn * 64 + np * 16 + b_roff;
        b_rowb[np] = row * 128;
        b_rx[np] = row & 7;
    }

    float acc[8][4];
    uint32_t acch[8][2];
    #pragma unroll
    for (int j = 0; j < 8; ++j) {
        #pragma unroll
        for (int q = 0; q < 4; ++q) acc[j][q] = 0.0f;
        acch[j][0] = 0u; acch[j][1] = 0u;
    }

    const int nst = Sq / 32;

    #pragma unroll
    for (int p = 0; p < 2; ++p) {
        const uint32_t tb = sm + p * PV_STG;
        const long k0 = (long)p * 32;
        cpasync16(tb + PV_BB + b_s0, Vp + k0 + bko);
        cpasync16(tb + PV_BB + b_s1, Vp + k0 + bko + 8);
        CP_COMMIT();
        float4 sv = *(const float4*)(Sp + k0);
        float p0 = __expf(sv.x - m) * ti, p1 = __expf(sv.y - m) * ti;
        float p2 = __expf(sv.z - m) * ti, p3 = __expf(sv.w - m) * ti;
        __half h0, l0, h1, l1, h2, l2, h3, l3;
        split1(p0, h0, l0); split1(p1, h1, l1);
        split1(p2, h2, l2); split1(p3, h3, l3);
        sts8(tb + a_hi, pack2(h0, h1), pack2(h2, h3));
        sts8(tb + a_lo, pack2(l0, l1), pack2(l2, l3));
    }

    int stg = 0;
    #pragma unroll 1
    for (int s = 0; s < nst; ++s) {
        if (s + 1 < nst) CP_WAIT1(); else CP_WAIT0();
        __syncthreads();

        const bool pf = (s + 2 < nst);
        int ps = stg + 2; if (ps >= NSTAGE) ps -= NSTAGE;
        const uint32_t pb = sm + ps * PV_STG;
        float4 sv;
        if (pf) {
            const long k2 = (long)(s + 2) * 32;
            cpasync16(pb + PV_BB + b_s0, Vp + k2 + bko);
            cpasync16(pb + PV_BB + b_s1, Vp + k2 + bko + 8);
            sv = *(const float4*)(Sp + k2);
        }

        const uint32_t tb = sm + stg * PV_STG;
        #pragma unroll
        for (int ks = 0; ks < 2; ++ks) {
            const int ca = ks * 2 + a_kh;
            const int cb = ks * 2 + b_kh;
            uint32_t Ah[4], Al[4], Bh[4][4];
            LDSM4(Ah, tb + a_rowb + (((ca + 0) ^ a_rx) << 4));
            LDSM4(Al, tb + a_rowb + (((ca + 4) ^ a_rx) << 4));
            #pragma unroll
            for (int np = 0; np < 4; ++np)
                LDSM4(Bh[np], tb + PV_BB + b_rowb[np] + ((cb ^ b_rx[np]) << 4));
            #pragma unroll
            for (int nt = 0; nt < 8; ++nt) {
                const int np = nt >> 1, s2 = (nt & 1) * 2;
                MMAF(acc[nt], Ah, Bh[np][s2], Bh[np][s2 + 1]);
            }
            #pragma unroll
            for (int nt = 0; nt < 8; ++nt) {
                const int np = nt >> 1, s2 = (nt & 1) * 2;
                MMAH(acch[nt], Al, Bh[np][s2], Bh[np][s2 + 1]);
            }
        }

        if (pf) {
            float p0 = __expf(sv.x - m) * ti, p1 = __expf(sv.y - m) * ti;
            float p2 = __expf(sv.z - m) * ti, p3 = __expf(sv.w - m) * ti;
            __half h0, l0, h1, l1, h2, l2, h3, l3;
            split1(p0, h0, l0); split1(p1, h1, l1);
            split1(p2, h2, l2); split1(p3, h3, l3);
            sts8(pb + a_hi, pack2(h0, h1), pack2(h2, h3));
            sts8(pb + a_lo, pack2(l0, l1), pack2(l2, l3));
        }
        CP_COMMIT();

        if (++stg == NSTAGE) stg = 0;
    }

    const int r_in = lane >> 2, c_in = (lane & 3) * 2;
    __half* Zb = Z + (long)(z / Hq) * Sq * (Hq * Dq) + (long)(z % Hq) * Dq;
    #pragma unroll
    for (int half = 0; half < 2; ++half) {
        const long row = row0 + wm * 16 + half * 8 + r_in;
        #pragma unroll
        for (int nt = 0; nt < 8; ++nt) {
            const int colg = (int)col0 + wn * 64 + nt * 8 + c_in;
            float2 cf = __half22float2(*reinterpret_cast<__half2*>(&acch[nt][half]));
            float v0 = (acc[nt][half * 2 + 0] + cf.x) * (1.0f / 128.0f);
            float v1 = (acc[nt][half * 2 + 1] + cf.y) * (1.0f / 128.0f);
            uint32_t hw = pack2(__float2half_rn(v0), __float2half_rn(v1));
            *(uint32_t*)(Zb + row * (Hq * Dq) + colg) = hw;
        }
    }
}

// ---------------------------------------------------------------------------
__global__ void __launch_bounds__(256) cvt3_kernel(const float* __restrict__ a,
                                                   const float* __restrict__ b,
                                                   const float* __restrict__ c,
                                                   __half* __restrict__ dst)
{
    const float* in = (blockIdx.y == 0) ? a : (blockIdx.y == 1) ? b : c;
    __half* out = dst + (long)blockIdx.y * X_PLANE;
    const long idx = (long)blockIdx.x * 256 + threadIdx.x;
    float4 v = ((const float4*)in)[idx];
    ((uint32_t*)out)[2 * idx]     = pack2(__float2half_rn(v.x), __float2half_rn(v.y));
    ((uint32_t*)out)[2 * idx + 1] = pack2(__float2half_rn(v.z), __float2half_rn(v.w));
}

__global__ void __launch_bounds__(256) tcvt3_kernel(const float* __restrict__ wq,
                                                    const float* __restrict__ wk,
                                                    const float* __restrict__ wv,
                                                    __half* __restrict__ dst)
{
    __shared__ float ts[32][33];
    const int tx = threadIdx.x, ty = threadIdx.y;
    const int mh = blockIdx.z;
    const int mm = mh >> 3, h = mh & 7;
    const float* in = ((mm == 0) ? wq : (mm == 1) ? wk : wv) + (long)h * DDc;
    __half* out = dst + (long)mm * W_PLANE + (long)h * DDc;
    const int r0 = blockIdx.y * 32, c0 = blockIdx.x * 32;
    #pragma unroll
    for (int i = 0; i < 4; ++i)
        ts[ty + 8 * i][tx] = in[(long)(r0 + ty + 8 * i) * Dq + c0 + tx];
    __syncthreads();
    #pragma unroll
    for (int i = 0; i < 4; ++i)
        out[(long)(c0 + ty + 8 * i) * Dq + r0 + tx] =
            __float2half_rn(ts[tx][ty + 8 * i] * 16.0f);
}

__global__ void __launch_bounds__(256) tsplit_wz_kernel(const float* __restrict__ in,
                                                        __half* __restrict__ outh)
{
    __shared__ float ts[32][33];
    const int tx = threadIdx.x, ty = threadIdx.y;
    const int r0 = blockIdx.y * 32, c0 = blockIdx.x * 32;
    const int R = Hq * Dq, C = Dq;
    #pragma unroll
    for (int i = 0; i < 4; ++i)
        ts[ty + 8 * i][tx] = in[(long)(r0 + ty + 8 * i) * C + c0 + tx];
    __syncthreads();
    #pragma unroll
    for (int i = 0; i < 4; ++i) {
        __half h, l;
        split1(ts[tx][ty + 8 * i] * 64.0f, h, l);
        const long o = (long)(c0 + ty + 8 * i) * R + r0 + tx;
        outh[o] = h;
        outh[o + W_PLANE] = l;
    }
}

// ---------------------------------------------------------------------------
__global__ void __launch_bounds__(256) softmax_stats_kernel(float* __restrict__ avg_out)
{
    const int r = blockIdx.x & (Sq - 1);
    const int b = blockIdx.x >> 11;
    const int tid = threadIdx.x;
    __shared__ float sr[8];

    float avg[8];
    #pragma unroll
    for (int i = 0; i < 8; ++i) avg[i] = 0.0f;

    #pragma unroll 1
    for (int h = 0; h < Hq; ++h) {
        const float* p = g_attn + (((long)b * Hq + h) * Sq + r) * Sq;

        float v[8];
        float mx = -1e30f;
        #pragma unroll
        for (int i = 0; i < 8; ++i) { v[i] = p[tid + i * 256]; mx = fmaxf(mx, v[i]); }
        #pragma unroll
        for (int o = 16; o > 0; o >>= 1) mx = fmaxf(mx, __shfl_xor_sync(~0u, mx, o));
        if ((tid & 31) == 0) sr[tid >> 5] = mx;
        __syncthreads();
        float mm = sr[0];
        #pragma unroll
        for (int i = 1; i < 8; ++i) mm = fmaxf(mm, sr[i]);
        __syncthreads();

        float s = 0.f;
        #pragma unroll
        for (int i = 0; i < 8; ++i) { v[i] = __expf(v[i] - mm); s += v[i]; }
        #pragma unroll
        for (int o = 16; o > 0; o >>= 1) s += __shfl_xor_sync(~0u, s, o);
        if ((tid & 31) == 0) sr[tid >> 5] = s;
        __syncthreads();
        float t = 0.f;
        #pragma unroll
        for (int i = 0; i < 8; ++i) t += sr[i];
        __syncthreads();

        const float inv = 1.0f / t;
        #pragma unroll
        for (int i = 0; i < 8; ++i) avg[i] += v[i] * inv;

        if (tid == 0) {
            g_m [((long)b * Hq + h) * Sq + r] = mm;
            g_ti[((long)b * Hq + h) * Sq + r] = 1024.0f / t;
        }
    }

    float* dst = avg_out + ((long)b * Sq + r) * Sq;
    #pragma unroll
    for (int i = 0; i < 8; ++i)
        dst[tid + i * 256] = avg[i] * 0.125f;
}

// ---------------------------------------------------------------------------
extern "C" void kernel_launch(void* const* d_in, const int* in_sizes, int n_in,
                              void* d_out, int out_size)
{
    (void)in_sizes; (void)n_in; (void)out_size;
    const float* Xq = (const float*)d_in[0];
    const float* Xk = (const float*)d_in[1];
    const float* Xv = (const float*)d_in[2];
    const float* Wq = (const float*)d_in[3];
    const float* Wk = (const float*)d_in[4];
    const float* Wv = (const float*)d_in[5];
    const float* Wz = (const float*)d_in[6];
    const float* bz = (const float*)d_in[7];
    float* out = (float*)d_out;
    float* attn_avg = out + (long)Bq * Sq * Dq;

    __half *px, *pw, *pwz, *pqk, *pvt, *pzs;
    float* pattn;
    cudaGetSymbolAddress((void**)&px, g_x);
    cudaGetSymbolAddress((void**)&pw, g_w);
    cudaGetSymbolAddress((void**)&pwz, g_wzt);
    cudaGetSymbolAddress((void**)&pqk, g_qk);
    cudaGetSymbolAddress((void**)&pvt, g_vts);
    cudaGetSymbolAddress((void**)&pzs, g_zs);
    cudaGetSymbolAddress((void**)&pattn, g_attn);

    cudaFuncSetAttribute(gemm_mma<0>, cudaFuncAttributeMaxDynamicSharedMemorySize, SMEM_SZ);
    cudaFuncSetAttribute(gemm_mma<1>, cudaFuncAttributeMaxDynamicSharedMemorySize, SMEM_SZ);
    cudaFuncSetAttribute(pv_kernel, cudaFuncAttributeMaxDynamicSharedMemorySize, PV_SMEM);

    const float inv4 = (float)(1.0 / pow((double)Dq, 0.25));

    // 1) convert inputs + weights
    cvt3_kernel<<<dim3((int)(X_PLANE / 1024), 3), 256>>>(Xq, Xk, Xv, px);
    {
        dim3 tb(32, 8);
        tcvt3_kernel<<<dim3(16, 16, 24), tb>>>(Wq, Wk, Wv, pw);
        tsplit_wz_kernel<<<dim3(16, 128, 1), tb>>>(Wz, pwz);
    }

    // 2) Q+K projections in one launch
    {
        dim3 grid(Dq / 128, Sq / 128, 32);
        Off oa = { 8, SDc, 1, 0 };
        Off ob = { 16, W_PLANE, 8, DDc };
        Off oc = { 16, QK_PLANE, 16, SDc };
        gemm_mma<0><<<grid, 256, SMEM_SZ>>>(px, 0, pw, 0, pqk,
                                            Dq, Dq, Dq, Dq, oa, ob, oc,
                                            inv4 * 0.25f, nullptr, 1);
    }
    // V projection (transposed output)
    {
        dim3 grid(Dq / 128, Sq / 128, 16);
        Off oa = { 8, SDc, 1, 0 };
        Off ob = { 1, 0, 8, DDc };
        Off oc = { 1, SDc, 1, 0 };
        gemm_mma<0><<<grid, 256, SMEM_SZ>>>(px + 2 * X_PLANE, 0, pw + 2 * W_PLANE, 0, pvt,
                                            Dq, Dq, Dq, Sq, oa, ob, oc,
                                            0.25f, nullptr, 2);
    }

    // 3) scores (fp32) = q_s.k_s / 16
    {
        dim3 grid(Sq / 128, Sq / 128, Bq * Hq);
        Off oa = { 1, SDc, 1, 0 };
        Off ob = { 1, SDc, 1, 0 };
        Off oc = { 1, SSc, 1, 0 };
        gemm_mma<0><<<grid, 256, SMEM_SZ>>>(pqk, 0, pqk + QK_PLANE, 0, pattn,
                                            Dq, Dq, Dq, Sq, oa, ob, oc,
                                            1.0f / 16.0f, nullptr, 0);
    }

    // 4) streaming softmax stats + head-average
    softmax_stats_kernel<<<Bq * Sq, 256>>>(attn_avg);

    // 5) PV with on-the-fly softmax probs
    pv_kernel<<<dim3(2, 32, Bq * Hq), 512, PV_SMEM>>>(pattn, pvt, pzs);

    // 6) out = (z_s . wz_s)/2048 + bz
    {
        dim3 grid(Dq / 128, (Bq * Sq) / 128, 1);
        Off oz = { 1, 0, 1, 0 };
        gemm_mma<1><<<grid, 256, SMEM_SZ>>>(pzs, 0, pwz, W_PLANE, out,
                                            Hq * Dq, Hq * Dq, Hq * Dq, Dq,
                                            oz, oz, oz, 1.0f / 2048.0f, bz, 0);
    }
}

// round 16
// speedup vs baseline: 1.0768x; 1.0768x over previous
#include <cuda_runtime.h>
#include <cuda_fp16.h>
#include <math.h>
#include <stdint.h>

#define Bq 2
#define Sq 2048
#define Dq 512
#define Hq 8

#define SDc  ((long)Sq * Dq)
#define SSc  ((long)Sq * Sq)
#define DDc  ((long)Dq * Dq)

#define X_PLANE    ((long)Bq * Sq * Dq)
#define W_PLANE    ((long)Hq * Dq * Dq)
#define QK_PLANE   ((long)Bq * Hq * Sq * Dq)
#define Z_PLANE    QK_PLANE

__device__ __align__(256) float g_attn[(long)Bq * Hq * Sq * Sq];
__device__ __align__(256) __half g_x  [3 * X_PLANE];
__device__ __align__(256) __half g_w  [3 * W_PLANE];
__device__ __align__(256) __half g_wzt[2 * W_PLANE];
__device__ __align__(256) __half g_qk [2 * QK_PLANE];
__device__ __align__(256) __half g_vts[QK_PLANE];
__device__ __align__(256) __half g_zs [Z_PLANE];
__device__ __align__(256) float g_m [(long)Bq * Hq * Sq];
__device__ __align__(256) float g_ti[(long)Bq * Hq * Sq];

struct Off { int dv; long s1; int md; long s2; };

__device__ __forceinline__ uint32_t smem_u32(const void* p) {
    uint32_t a;
    asm("{ .reg .u64 t; cvta.to.shared.u64 t, %1; cvt.u32.u64 %0, t; }" : "=r"(a) : "l"(p));
    return a;
}
__device__ __forceinline__ void cpasync16(uint32_t dst, const void* src) {
    asm volatile("cp.async.cg.shared.global [%0], [%1], 16;" :: "r"(dst), "l"(src) : "memory");
}
#define CP_COMMIT() asm volatile("cp.async.commit_group;" ::: "memory")
#define CP_WAIT2()  asm volatile("cp.async.wait_group 2;" ::: "memory")

#define LDSM4(r, a) \
    asm volatile("ldmatrix.sync.aligned.m8n8.x4.shared.b16 {%0,%1,%2,%3}, [%4];" \
        : "=r"((r)[0]), "=r"((r)[1]), "=r"((r)[2]), "=r"((r)[3]) : "r"(a))

#define MMAF(c, a, b0, b1) \
    asm volatile("mma.sync.aligned.m16n8k16.row.col.f32.f16.f16.f32 " \
        "{%0,%1,%2,%3},{%4,%5,%6,%7},{%8,%9},{%0,%1,%2,%3};" \
        : "+f"((c)[0]), "+f"((c)[1]), "+f"((c)[2]), "+f"((c)[3]) \
        : "r"((a)[0]), "r"((a)[1]), "r"((a)[2]), "r"((a)[3]), "r"(b0), "r"(b1))

#define MMAH(c, a, b0, b1) \
    asm volatile("mma.sync.aligned.m16n8k16.row.col.f16.f16.f16.f16 " \
        "{%0,%1},{%2,%3,%4,%5},{%6,%7},{%0,%1};" \
        : "+r"((c)[0]), "+r"((c)[1]) \
        : "r"((a)[0]), "r"((a)[1]), "r"((a)[2]), "r"((a)[3]), "r"(b0), "r"(b1))

__device__ __forceinline__ void split1(float x, __half& h, __half& l) {
    h = __float2half_rn(x);
    l = __float2half_rn(x - __half2float(h));
}
__device__ __forceinline__ uint32_t pack2(__half a, __half b) {
    __half2 t; t.x = a; t.y = b;
    return *reinterpret_cast<uint32_t*>(&t);
}
__device__ __forceinline__ void sts8(uint32_t addr, uint32_t x, uint32_t y) {
    asm volatile("st.shared.v2.b32 [%0], {%1,%2};" :: "r"(addr), "r"(x), "r"(y) : "memory");
}

#define STAGE_B  16384
#define STAGE_SZ 32768
#define NSTAGE   4
#define SMEM_SZ  (NSTAGE * STAGE_SZ)
#define GTHREADS 512

// ---------------------------------------------------------------------------
// fp16 HMMA TN GEMM — 512 threads, warp tile 32x32 (R14 config), 4-stage pipe.
// PMASK: 0 = hi-pass only; 1 adds Ah.Bl f16acc.
// mode 0: fp32 out (+bias). mode 1: fp16 hi out. mode 2: fp16 hi transposed.
// z >= zsplit: switch to (Cv2, ldc2, alpha2, mode 2, oc2 indexed by z-zsplit).
// ---------------------------------------------------------------------------
template <int PMASK>
__global__ void __launch_bounds__(GTHREADS, 1)
gemm_mma(const __half* __restrict__ A, long aplane,
         const __half* __restrict__ B, long bplane,
         void* Cv,
         int K, int lda, int ldb, int ldc,
         Off oa, Off ob, Off oc,
         float alpha, const float* __restrict__ bias, int mode,
         int zsplit, void* Cv2, int ldc2, float alpha2, Off oc2)
{
    constexpr bool needBlo = (PMASK & 1) != 0;

    extern __shared__ char smem[];
    const uint32_t sm = smem_u32(smem);
    const int tid = threadIdx.x, wid = tid >> 5, lane = tid & 31;
    const int z = blockIdx.z;

    const __half* Ahp = A + (long)(z / oa.dv) * oa.s1 + (long)(z % oa.md) * oa.s2;
    const __half* Bhp = B + (long)(z / ob.dv) * ob.s1 + (long)(z % ob.md) * ob.s2;

    long coff;
    if (z >= zsplit) {
        Cv = Cv2; ldc = ldc2; alpha = alpha2; mode = 2;
        const int z2 = z - zsplit;
        coff = (long)(z2 / oc2.dv) * oc2.s1 + (long)(z2 % oc2.md) * oc2.s2;
    } else {
        coff = (long)(z / oc.dv) * oc.s1 + (long)(z % oc.md) * oc.s2;
    }

    const long row0 = (long)blockIdx.y * 128;
    const long col0 = (long)blockIdx.x * 128;

    const int lrow = tid >> 2;
    const int c0   = (tid & 3) * 2;
    const int lpl  = c0 >> 2;
    const __half* Asrc = Ahp + (row0 + lrow) * lda + (c0 & 3) * 8;
    const __half* Bsrc = (lpl ? Bhp + bplane : Bhp) + (col0 + lrow) * ldb + (c0 & 3) * 8;
    const bool doA = (lpl == 0);
    const bool doB = (lpl == 0) || needBlo;
    uint32_t soff[2];
    #pragma unroll
    for (int j = 0; j < 2; ++j)
        soff[j] = lrow * 128 + (((c0 + j) ^ (lrow & 7)) << 4);

    const int wm = wid & 3, wn = wid >> 2;
    const int g = lane >> 3, r8 = lane & 7;
    const int a_roff = ((g & 1) << 3) + r8;
    const int a_kh   = g >> 1;
    const int b_roff = ((g >> 1) << 3) + r8;
    const int b_kh   = g & 1;

    uint32_t a_row[2], a_rx[2];
    #pragma unroll
    for (int mt = 0; mt < 2; ++mt) {
        const int row = wm * 32 + mt * 16 + a_roff;
        a_row[mt] = row * 128;
        a_rx[mt] = row & 7;
    }
    uint32_t b_row[2], b_rx[2];
    #pragma unroll
    for (int np = 0; np < 2; ++np) {
        const int row = wn * 32 + np * 16 + b_roff;
        b_row[np] = row * 128;
        b_rx[np] = row & 7;
    }

    float acc[2][4][4];
    uint32_t acch[2][4][2];
    #pragma unroll
    for (int i = 0; i < 2; ++i)
        #pragma unroll
        for (int j = 0; j < 4; ++j) {
            #pragma unroll
            for (int q = 0; q < 4; ++q) acc[i][j][q] = 0.0f;
            acch[i][j][0] = 0u; acch[i][j][1] = 0u;
        }

    const int nst = K / 32;

    // prologue: stages 0..2
    #pragma unroll
    for (int p = 0; p < 3; ++p) {
        if (p < nst) {
            const uint32_t tb = sm + p * STAGE_SZ;
            const long k0 = (long)p * 32;
            #pragma unroll
            for (int j = 0; j < 2; ++j) {
                if (doA) cpasync16(tb + soff[j], Asrc + k0 + j * 8);
                if (doB) cpasync16(tb + STAGE_B + soff[j], Bsrc + k0 + j * 8);
            }
        }
        CP_COMMIT();
    }

    int stg = 0;
    for (int s = 0; s < nst; ++s) {
        CP_WAIT2();
        __syncthreads();

        const uint32_t tb = sm + stg * STAGE_SZ;
        const uint32_t tba = tb, tbb = tb + STAGE_B;

        #pragma unroll
        for (int ks = 0; ks < 2; ++ks) {
            const int ca = ks * 2 + a_kh;
            const int cb = ks * 2 + b_kh;

            uint32_t Ahr[2][4], Bhr[2][4];
            #pragma unroll
            for (int mt = 0; mt < 2; ++mt)
                LDSM4(Ahr[mt], tba + a_row[mt] + ((ca ^ a_rx[mt]) << 4));
            #pragma unroll
            for (int np = 0; np < 2; ++np)
                LDSM4(Bhr[np], tbb + b_row[np] + ((cb ^ b_rx[np]) << 4));
            #pragma unroll
            for (int mt = 0; mt < 2; ++mt)
                #pragma unroll
                for (int nt = 0; nt < 4; ++nt) {
                    const int np = nt >> 1, s2 = (nt & 1) * 2;
                    MMAF(acc[mt][nt], Ahr[mt], Bhr[np][s2], Bhr[np][s2 + 1]);
                }

            if (needBlo) {
                uint32_t Blr[2][4];
                #pragma unroll
                for (int np = 0; np < 2; ++np)
                    LDSM4(Blr[np], tbb + b_row[np] + (((cb + 4) ^ b_rx[np]) << 4));
                #pragma unroll
                for (int mt = 0; mt < 2; ++mt)
                    #pragma unroll
                    for (int nt = 0; nt < 4; ++nt) {
                        const int np = nt >> 1, s2 = (nt & 1) * 2;
                        MMAH(acch[mt][nt], Ahr[mt], Blr[np][s2], Blr[np][s2 + 1]);
                    }
            }
        }

        if (s + 3 < nst) {
            int ps = stg + 3; if (ps >= NSTAGE) ps -= NSTAGE;
            const uint32_t pb = sm + ps * STAGE_SZ;
            const long k0 = (long)(s + 3) * 32;
            #pragma unroll
            for (int j = 0; j < 2; ++j) {
                if (doA) cpasync16(pb + soff[j], Asrc + k0 + j * 8);
                if (doB) cpasync16(pb + STAGE_B + soff[j], Bsrc + k0 + j * 8);
            }
        }
        CP_COMMIT();

        if (++stg == NSTAGE) stg = 0;
    }

    const int r_in = lane >> 2, c_in = (lane & 3) * 2;
    #pragma unroll
    for (int mt = 0; mt < 2; ++mt) {
        #pragma unroll
        for (int half = 0; half < 2; ++half) {
            const long row = row0 + wm * 32 + mt * 16 + half * 8 + r_in;
            #pragma unroll
            for (int nt = 0; nt < 4; ++nt) {
                const int colg = (int)col0 + wn * 32 + nt * 8 + c_in;
                float v0 = acc[mt][nt][half * 2 + 0];
                float v1 = acc[mt][nt][half * 2 + 1];
                if (PMASK) {
                    float2 cf = __half22float2(*reinterpret_cast<__half2*>(&acch[mt][nt][half]));
                    v0 += cf.x;
                    v1 += cf.y;
                }
                v0 *= alpha;
                v1 *= alpha;
                if (mode == 0) {
                    if (bias) { v0 += bias[colg]; v1 += bias[colg + 1]; }
                    *(float2*)((float*)Cv + coff + row * ldc + colg) = make_float2(v0, v1);
                } else if (mode == 1) {
                    uint32_t hw = pack2(__float2half_rn(v0), __float2half_rn(v1));
                    *(uint32_t*)((__half*)Cv + coff + row * ldc + colg) = hw;
                } else {
                    __half* Ch = (__half*)Cv + coff;
                    Ch[(long)colg * ldc + row] = __float2half_rn(v0);
                    Ch[(long)(colg + 1) * ldc + row] = __float2half_rn(v1);
                }
            }
        }
    }
}

// ---------------------------------------------------------------------------
// PV kernel: probs on the fly; 64x256 tile; 4-stage pipeline.
// ---------------------------------------------------------------------------
#define PV_BB   8192
#define PV_STG  40960
#define PV_SMEM (NSTAGE * PV_STG)

__global__ void __launch_bounds__(512, 1)
pv_kernel(const float* __restrict__ S, const __half* __restrict__ V,
          __half* __restrict__ Z)
{
    extern __shared__ char smem[];
    const uint32_t sm = smem_u32(smem);
    const int tid = threadIdx.x, wid = tid >> 5, lane = tid & 31;
    const int z = blockIdx.z;
    const long row0 = (long)blockIdx.y * 64;
    const long col0 = (long)blockIdx.x * 256;

    const int ar  = tid >> 3;
    const int seg = tid & 7;
    const long rowg = row0 + ar;
    const float* Sp = S + (long)z * SSc + rowg * Sq + seg * 4;
    const float m  = g_m [(long)z * Sq + rowg];
    const float ti = g_ti[(long)z * Sq + rowg];
    const uint32_t a_hi = ar * 128 + ((((seg >> 1) + 0) ^ (ar & 7)) << 4) + (seg & 1) * 8;
    const uint32_t a_lo = ar * 128 + ((((seg >> 1) + 4) ^ (ar & 7)) << 4) + (seg & 1) * 8;

    const int br = tid >> 1;
    const int bc = (tid & 1) * 2;
    const __half* Vp = V + (long)z * SDc + (col0 + br) * Sq;
    const uint32_t b_s0 = br * 128 + (((bc + 0) ^ (br & 7)) << 4);
    const uint32_t b_s1 = br * 128 + (((bc + 1) ^ (br & 7)) << 4);
    const int bko = bc * 8;

    const int wm = wid & 3, wn = wid >> 2;
    const int g = lane >> 3, r8 = lane & 7;
    const int a_roff = ((g & 1) << 3) + r8;
    const int a_kh   = g >> 1;
    const int b_roff = ((g >> 1) << 3) + r8;
    const int b_kh   = g & 1;

    const int arc = wm * 16 + a_roff;
    const uint32_t a_rowb = arc * 128;
    const uint32_t a_rx = arc & 7;
    uint32_t b_rowb[4], b_rx[4];
    #pragma unroll
    for (int np = 0; np < 4; ++np) {
        const int row = wn * 64 + np * 16 + b_roff;
        b_rowb[np] = row * 128;
        b_rx[np] = row & 7;
    }

    float acc[8][4];
    uint32_t acch[8][2];
    #pragma unroll
    for (int j = 0; j < 8; ++j) {
        #pragma unroll
        for (int q = 0; q < 4; ++q) acc[j][q] = 0.0f;
        acch[j][0] = 0u; acch[j][1] = 0u;
    }

    const int nst = Sq / 32;

    #pragma unroll
    for (int p = 0; p < 3; ++p) {
        const uint32_t tb = sm + p * PV_STG;
        const long k0 = (long)p * 32;
        cpasync16(tb + PV_BB + b_s0, Vp + k0 + bko);
        cpasync16(tb + PV_BB + b_s1, Vp + k0 + bko + 8);
        CP_COMMIT();
        float4 sv = *(const float4*)(Sp + k0);
        float p0 = __expf(sv.x - m) * ti, p1 = __expf(sv.y - m) * ti;
        float p2 = __expf(sv.z - m) * ti, p3 = __expf(sv.w - m) * ti;
        __half h0, l0, h1, l1, h2, l2, h3, l3;
        split1(p0, h0, l0); split1(p1, h1, l1);
        split1(p2, h2, l2); split1(p3, h3, l3);
        sts8(tb + a_hi, pack2(h0, h1), pack2(h2, h3));
        sts8(tb + a_lo, pack2(l0, l1), pack2(l2, l3));
    }

    int stg = 0;
    #pragma unroll 1
    for (int s = 0; s < nst; ++s) {
        CP_WAIT2();
        __syncthreads();

        const bool pf = (s + 3 < nst);
        int ps = stg + 3; if (ps >= NSTAGE) ps -= NSTAGE;
        const uint32_t pb = sm + ps * PV_STG;
        float4 sv;
        if (pf) {
            const long k2 = (long)(s + 3) * 32;
            cpasync16(pb + PV_BB + b_s0, Vp + k2 + bko);
            cpasync16(pb + PV_BB + b_s1, Vp + k2 + bko + 8);
            sv = *(const float4*)(Sp + k2);
        }

        const uint32_t tb = sm + stg * PV_STG;
        #pragma unroll
        for (int ks = 0; ks < 2; ++ks) {
            const int ca = ks * 2 + a_kh;
            const int cb = ks * 2 + b_kh;
            uint32_t Ah[4], Al[4], Bh[4][4];
            LDSM4(Ah, tb + a_rowb + (((ca + 0) ^ a_rx) << 4));
            LDSM4(Al, tb + a_rowb + (((ca + 4) ^ a_rx) << 4));
            #pragma unroll
            for (int np = 0; np < 4; ++np)
                LDSM4(Bh[np], tb + PV_BB + b_rowb[np] + ((cb ^ b_rx[np]) << 4));
            #pragma unroll
            for (int nt = 0; nt < 8; ++nt) {
                const int np = nt >> 1, s2 = (nt & 1) * 2;
                MMAF(acc[nt], Ah, Bh[np][s2], Bh[np][s2 + 1]);
            }
            #pragma unroll
            for (int nt = 0; nt < 8; ++nt) {
                const int np = nt >> 1, s2 = (nt & 1) * 2;
                MMAH(acch[nt], Al, Bh[np][s2], Bh[np][s2 + 1]);
            }
        }

        if (pf) {
            float p0 = __expf(sv.x - m) * ti, p1 = __expf(sv.y - m) * ti;
            float p2 = __expf(sv.z - m) * ti, p3 = __expf(sv.w - m) * ti;
            __half h0, l0, h1, l1, h2, l2, h3, l3;
            split1(p0, h0, l0); split1(p1, h1, l1);
            split1(p2, h2, l2); split1(p3, h3, l3);
            sts8(pb + a_hi, pack2(h0, h1), pack2(h2, h3));
            sts8(pb + a_lo, pack2(l0, l1), pack2(l2, l3));
        }
        CP_COMMIT();

        if (++stg == NSTAGE) stg = 0;
    }

    const int r_in = lane >> 2, c_in = (lane & 3) * 2;
    __half* Zb = Z + (long)(z / Hq) * Sq * (Hq * Dq) + (long)(z % Hq) * Dq;
    #pragma unroll
    for (int half = 0; half < 2; ++half) {
        const long row = row0 + wm * 16 + half * 8 + r_in;
        #pragma unroll
        for (int nt = 0; nt < 8; ++nt) {
            const int colg = (int)col0 + wn * 64 + nt * 8 + c_in;
            float2 cf = __half22float2(*reinterpret_cast<__half2*>(&acch[nt][half]));
            float v0 = (acc[nt][half * 2 + 0] + cf.x) * (1.0f / 128.0f);
            float v1 = (acc[nt][half * 2 + 1] + cf.y) * (1.0f / 128.0f);
            uint32_t hw = pack2(__float2half_rn(v0), __float2half_rn(v1));
            *(uint32_t*)(Zb + row * (Hq * Dq) + colg) = hw;
        }
    }
}

// ---------------------------------------------------------------------------
__global__ void __launch_bounds__(256) cvt3_kernel(const float* __restrict__ a,
                                                   const float* __restrict__ b,
                                                   const float* __restrict__ c,
                                                   __half* __restrict__ dst)
{
    const float* in = (blockIdx.y == 0) ? a : (blockIdx.y == 1) ? b : c;
    __half* out = dst + (long)blockIdx.y * X_PLANE;
    const long idx = (long)blockIdx.x * 256 + threadIdx.x;
    float4 v = ((const float4*)in)[idx];
    ((uint32_t*)out)[2 * idx]     = pack2(__float2half_rn(v.x), __float2half_rn(v.y));
    ((uint32_t*)out)[2 * idx + 1] = pack2(__float2half_rn(v.z), __float2half_rn(v.w));
}

__global__ void __launch_bounds__(256) tcvt3_kernel(const float* __restrict__ wq,
                                                    const float* __restrict__ wk,
                                                    const float* __restrict__ wv,
                                                    __half* __restrict__ dst)
{
    __shared__ float ts[32][33];
    const int tx = threadIdx.x, ty = threadIdx.y;
    const int mh = blockIdx.z;
    const int mm = mh >> 3, h = mh & 7;
    const float* in = ((mm == 0) ? wq : (mm == 1) ? wk : wv) + (long)h * DDc;
    __half* out = dst + (long)mm * W_PLANE + (long)h * DDc;
    const int r0 = blockIdx.y * 32, c0 = blockIdx.x * 32;
    #pragma unroll
    for (int i = 0; i < 4; ++i)
        ts[ty + 8 * i][tx] = in[(long)(r0 + ty + 8 * i) * Dq + c0 + tx];
    __syncthreads();
    #pragma unroll
    for (int i = 0; i < 4; ++i)
        out[(long)(c0 + ty + 8 * i) * Dq + r0 + tx] =
            __float2half_rn(ts[tx][ty + 8 * i] * 16.0f);
}

__global__ void __launch_bounds__(256) tsplit_wz_kernel(const float* __restrict__ in,
                                                        __half* __restrict__ outh)
{
    __shared__ float ts[32][33];
    const int tx = threadIdx.x, ty = threadIdx.y;
    const int r0 = blockIdx.y * 32, c0 = blockIdx.x * 32;
    const int R = Hq * Dq, C = Dq;
    #pragma unroll
    for (int i = 0; i < 4; ++i)
        ts[ty + 8 * i][tx] = in[(long)(r0 + ty + 8 * i) * C + c0 + tx];
    __syncthreads();
    #pragma unroll
    for (int i = 0; i < 4; ++i) {
        __half h, l;
        split1(ts[tx][ty + 8 * i] * 64.0f, h, l);
        const long o = (long)(c0 + ty + 8 * i) * R + r0 + tx;
        outh[o] = h;
        outh[o + W_PLANE] = l;
    }
}

// ---------------------------------------------------------------------------
__global__ void __launch_bounds__(256) softmax_stats_kernel(float* __restrict__ avg_out)
{
    const int r = blockIdx.x & (Sq - 1);
    const int b = blockIdx.x >> 11;
    const int tid = threadIdx.x;
    __shared__ float sr[8];

    float avg[8];
    #pragma unroll
    for (int i = 0; i < 8; ++i) avg[i] = 0.0f;

    #pragma unroll 1
    for (int h = 0; h < Hq; ++h) {
        const float* p = g_attn + (((long)b * Hq + h) * Sq + r) * Sq;

        float v[8];
        float mx = -1e30f;
        #pragma unroll
        for (int i = 0; i < 8; ++i) { v[i] = p[tid + i * 256]; mx = fmaxf(mx, v[i]); }
        #pragma unroll
        for (int o = 16; o > 0; o >>= 1) mx = fmaxf(mx, __shfl_xor_sync(~0u, mx, o));
        if ((tid & 31) == 0) sr[tid >> 5] = mx;
        __syncthreads();
        float mm = sr[0];
        #pragma unroll
        for (int i = 1; i < 8; ++i) mm = fmaxf(mm, sr[i]);
        __syncthreads();

        float s = 0.f;
        #pragma unroll
        for (int i = 0; i < 8; ++i) { v[i] = __expf(v[i] - mm); s += v[i]; }
        #pragma unroll
        for (int o = 16; o > 0; o >>= 1) s += __shfl_xor_sync(~0u, s, o);
        if ((tid & 31) == 0) sr[tid >> 5] = s;
        __syncthreads();
        float t = 0.f;
        #pragma unroll
        for (int i = 0; i < 8; ++i) t += sr[i];
        __syncthreads();

        const float inv = 1.0f / t;
        #pragma unroll
        for (int i = 0; i < 8; ++i) avg[i] += v[i] * inv;

        if (tid == 0) {
            g_m [((long)b * Hq + h) * Sq + r] = mm;
            g_ti[((long)b * Hq + h) * Sq + r] = 1024.0f / t;
        }
    }

    float* dst = avg_out + ((long)b * Sq + r) * Sq;
    #pragma unroll
    for (int i = 0; i < 8; ++i)
        dst[tid + i * 256] = avg[i] * 0.125f;
}

// ---------------------------------------------------------------------------
extern "C" void kernel_launch(void* const* d_in, const int* in_sizes, int n_in,
                              void* d_out, int out_size)
{
    (void)in_sizes; (void)n_in; (void)out_size;
    const float* Xq = (const float*)d_in[0];
    const float* Xk = (const float*)d_in[1];
    const float* Xv = (const float*)d_in[2];
    const float* Wq = (const float*)d_in[3];
    const float* Wk = (const float*)d_in[4];
    const float* Wv = (const float*)d_in[5];
    const float* Wz = (const float*)d_in[6];
    const float* bz = (const float*)d_in[7];
    float* out = (float*)d_out;
    float* attn_avg = out + (long)Bq * Sq * Dq;

    __half *px, *pw, *pwz, *pqk, *pvt, *pzs;
    float* pattn;
    cudaGetSymbolAddress((void**)&px, g_x);
    cudaGetSymbolAddress((void**)&pw, g_w);
    cudaGetSymbolAddress((void**)&pwz, g_wzt);
    cudaGetSymbolAddress((void**)&pqk, g_qk);
    cudaGetSymbolAddress((void**)&pvt, g_vts);
    cudaGetSymbolAddress((void**)&pzs, g_zs);
    cudaGetSymbolAddress((void**)&pattn, g_attn);

    cudaFuncSetAttribute(gemm_mma<0>, cudaFuncAttributeMaxDynamicSharedMemorySize, SMEM_SZ);
    cudaFuncSetAttribute(gemm_mma<1>, cudaFuncAttributeMaxDynamicSharedMemorySize, SMEM_SZ);
    cudaFuncSetAttribute(pv_kernel, cudaFuncAttributeMaxDynamicSharedMemorySize, PV_SMEM);

    const float inv4 = (float)(1.0 / pow((double)Dq, 0.25));
    const Off noff = { 1, 0, 1, 0 };
    const int ZBIG = 1 << 30;

    // 1) convert inputs + weights
    cvt3_kernel<<<dim3((int)(X_PLANE / 1024), 3), 256>>>(Xq, Xk, Xv, px);
    {
        dim3 tb(32, 8);
        tcvt3_kernel<<<dim3(16, 16, 24), tb>>>(Wq, Wk, Wv, pw);
        tsplit_wz_kernel<<<dim3(16, 128, 1), tb>>>(Wz, pwz);
    }

    // 2) Q+K+V projections in ONE launch (z 0..31 = QK mode 1; z 32..47 = V mode 2)
    {
        dim3 grid(Dq / 128, Sq / 128, 48);
        Off oa = { 8, SDc, 1, 0 };                 // z/8 walks xq_b0..xv_b1
        Off ob = { 16, W_PLANE, 8, DDc };          // z/16 -> wq/wk/wv; z%8 -> h
        Off oc = { 16, QK_PLANE, 16, SDc };        // q_s | k_s planes
        Off ocv = { 1, SDc, 1, 0 };                // V: (z-32)*SD
        gemm_mma<0><<<grid, GTHREADS, SMEM_SZ>>>(px, 0, pw, 0, pqk,
                                                 Dq, Dq, Dq, Dq, oa, ob, oc,
                                                 inv4 * 0.25f, nullptr, 1,
                                                 32, pvt, Sq, 0.25f, ocv);
    }

    // 3) scores (fp32) = q_s.k_s / 16
    {
        dim3 grid(Sq / 128, Sq / 128, Bq * Hq);
        Off oa = { 1, SDc, 1, 0 };
        Off ob = { 1, SDc, 1, 0 };
        Off oc = { 1, SSc, 1, 0 };
        gemm_mma<0><<<grid, GTHREADS, SMEM_SZ>>>(pqk, 0, pqk + QK_PLANE, 0, pattn,
                                                 Dq, Dq, Dq, Sq, oa, ob, oc,
                                                 1.0f / 16.0f, nullptr, 0,
                                                 ZBIG, nullptr, 0, 0.0f, noff);
    }

    // 4) streaming softmax stats + head-average
    softmax_stats_kernel<<<Bq * Sq, 256>>>(attn_avg);

    // 5) PV with on-the-fly softmax probs
    pv_kernel<<<dim3(2, 32, Bq * Hq), 512, PV_SMEM>>>(pattn, pvt, pzs);

    // 6) out = (z_s . wz_s)/2048 + bz
    {
        dim3 grid(Dq / 128, (Bq * Sq) / 128, 1);
        gemm_mma<1><<<grid, GTHREADS, SMEM_SZ>>>(pzs, 0, pwz, W_PLANE, out,
                                                 Hq * Dq, Hq * Dq, Hq * Dq, Dq,
                                                 noff, noff, noff, 1.0f / 2048.0f, bz, 0,
                                                 ZBIG, nullptr, 0, 0.0f, noff);
    }
}

// round 17
// speedup vs baseline: 1.1043x; 1.0255x over previous
#include <cuda_runtime.h>
#include <cuda_fp16.h>
#include <math.h>
#include <stdint.h>

#define Bq 2
#define Sq 2048
#define Dq 512
#define Hq 8

#define SDc  ((long)Sq * Dq)
#define SSc  ((long)Sq * Sq)
#define DDc  ((long)Dq * Dq)

#define X_PLANE    ((long)Bq * Sq * Dq)
#define W_PLANE    ((long)Hq * Dq * Dq)
#define QK_PLANE   ((long)Bq * Hq * Sq * Dq)
#define Z_PLANE    QK_PLANE

__device__ __align__(256) float g_attn[(long)Bq * Hq * Sq * Sq];
__device__ __align__(256) __half g_x  [3 * X_PLANE];
__device__ __align__(256) __half g_w  [3 * W_PLANE];
__device__ __align__(256) __half g_wzt[2 * W_PLANE];
__device__ __align__(256) __half g_qk [2 * QK_PLANE];
__device__ __align__(256) __half g_vts[QK_PLANE];
__device__ __align__(256) __half g_zs [Z_PLANE];
__device__ __align__(256) float g_m [(long)Bq * Hq * Sq];
__device__ __align__(256) float g_ti[(long)Bq * Hq * Sq];

struct Off { int dv; long s1; int md; long s2; };

__device__ __forceinline__ uint32_t smem_u32(const void* p) {
    uint32_t a;
    asm("{ .reg .u64 t; cvta.to.shared.u64 t, %1; cvt.u32.u64 %0, t; }" : "=r"(a) : "l"(p));
    return a;
}
__device__ __forceinline__ void cpasync16(uint32_t dst, const void* src) {
    asm volatile("cp.async.cg.shared.global [%0], [%1], 16;" :: "r"(dst), "l"(src) : "memory");
}
#define CP_COMMIT() asm volatile("cp.async.commit_group;" ::: "memory")
#define CP_WAIT2()  asm volatile("cp.async.wait_group 2;" ::: "memory")

#define LDSM4(r, a) \
    asm volatile("ldmatrix.sync.aligned.m8n8.x4.shared.b16 {%0,%1,%2,%3}, [%4];" \
        : "=r"((r)[0]), "=r"((r)[1]), "=r"((r)[2]), "=r"((r)[3]) : "r"(a))

#define MMAF(c, a, b0, b1) \
    asm volatile("mma.sync.aligned.m16n8k16.row.col.f32.f16.f16.f32 " \
        "{%0,%1,%2,%3},{%4,%5,%6,%7},{%8,%9},{%0,%1,%2,%3};" \
        : "+f"((c)[0]), "+f"((c)[1]), "+f"((c)[2]), "+f"((c)[3]) \
        : "r"((a)[0]), "r"((a)[1]), "r"((a)[2]), "r"((a)[3]), "r"(b0), "r"(b1))

#define MMAH(c, a, b0, b1) \
    asm volatile("mma.sync.aligned.m16n8k16.row.col.f16.f16.f16.f16 " \
        "{%0,%1},{%2,%3,%4,%5},{%6,%7},{%0,%1};" \
        : "+r"((c)[0]), "+r"((c)[1]) \
        : "r"((a)[0]), "r"((a)[1]), "r"((a)[2]), "r"((a)[3]), "r"(b0), "r"(b1))

__device__ __forceinline__ void split1(float x, __half& h, __half& l) {
    h = __float2half_rn(x);
    l = __float2half_rn(x - __half2float(h));
}
__device__ __forceinline__ uint32_t pack2(__half a, __half b) {
    __half2 t; t.x = a; t.y = b;
    return *reinterpret_cast<uint32_t*>(&t);
}
__device__ __forceinline__ void sts8(uint32_t addr, uint32_t x, uint32_t y) {
    asm volatile("st.shared.v2.b32 [%0], {%1,%2};" :: "r"(addr), "r"(x), "r"(y) : "memory");
}

#define STAGE_B  16384
#define STAGE_SZ 32768
#define NSTAGE   4
#define SMEM_SZ  (NSTAGE * STAGE_SZ)
#define GTHREADS 512

// ---------------------------------------------------------------------------
// fp16 HMMA TN GEMM — 512 threads, warp tile 32x32, 4-stage cp.async pipe.
// KCH = 64 (hi-only rows, 8 barriers): PMASK must be 0.
// KCH = 32 (rows = [32 hi | 32 lo]): PMASK 0/1; PMASK=1 adds Ah.Bl f16acc.
// mode 0: fp32 out (+bias). mode 1: fp16 hi out. mode 2: fp16 hi transposed.
// z >= zsplit: switch to (Cv2, ldc2, alpha2, mode 2, oc2 indexed by z-zsplit).
// ---------------------------------------------------------------------------
template <int PMASK, int KCH>
__global__ void __launch_bounds__(GTHREADS, 1)
gemm_mma(const __half* __restrict__ A, long aplane,
         const __half* __restrict__ B, long bplane,
         void* Cv,
         int K, int lda, int ldb, int ldc,
         Off oa, Off ob, Off oc,
         float alpha, const float* __restrict__ bias, int mode,
         int zsplit, void* Cv2, int ldc2, float alpha2, Off oc2)
{
    constexpr bool needBlo = (PMASK & 1) != 0;
    constexpr int NKS = KCH / 16;

    extern __shared__ char smem[];
    const uint32_t sm = smem_u32(smem);
    const int tid = threadIdx.x, wid = tid >> 5, lane = tid & 31;
    const int z = blockIdx.z;

    const __half* Ahp = A + (long)(z / oa.dv) * oa.s1 + (long)(z % oa.md) * oa.s2;
    const __half* Bhp = B + (long)(z / ob.dv) * ob.s1 + (long)(z % ob.md) * ob.s2;

    long coff;
    if (z >= zsplit) {
        Cv = Cv2; ldc = ldc2; alpha = alpha2; mode = 2;
        const int z2 = z - zsplit;
        coff = (long)(z2 / oc2.dv) * oc2.s1 + (long)(z2 % oc2.md) * oc2.s2;
    } else {
        coff = (long)(z / oc.dv) * oc.s1 + (long)(z % oc.md) * oc.s2;
    }

    const long row0 = (long)blockIdx.y * 128;
    const long col0 = (long)blockIdx.x * 128;

    // loader: 4 threads/row, 2 chunks each.
    // KCH=64: chunks 0-7 all hi, k = chunk*8. KCH=32: chunks 0-3 hi, 4-7 lo plane.
    const int lrow = tid >> 2;
    const int c0   = (tid & 3) * 2;
    const int kofs = (KCH == 64) ? c0 * 8 : (c0 & 3) * 8;
    const int lpl  = (KCH == 64) ? 0 : (c0 >> 2);
    const __half* Asrc = Ahp + (row0 + lrow) * lda + kofs;
    const __half* Bsrc = (lpl ? Bhp + bplane : Bhp) + (col0 + lrow) * ldb + kofs;
    const bool doA = (lpl == 0);
    const bool doB = (lpl == 0) || needBlo;
    uint32_t soff[2];
    #pragma unroll
    for (int j = 0; j < 2; ++j)
        soff[j] = lrow * 128 + (((c0 + j) ^ (lrow & 7)) << 4);

    const int wm = wid & 3, wn = wid >> 2;
    const int g = lane >> 3, r8 = lane & 7;
    const int a_roff = ((g & 1) << 3) + r8;
    const int a_kh   = g >> 1;
    const int b_roff = ((g >> 1) << 3) + r8;
    const int b_kh   = g & 1;

    uint32_t a_row[2], a_rx[2];
    #pragma unroll
    for (int mt = 0; mt < 2; ++mt) {
        const int row = wm * 32 + mt * 16 + a_roff;
        a_row[mt] = row * 128;
        a_rx[mt] = row & 7;
    }
    uint32_t b_row[2], b_rx[2];
    #pragma unroll
    for (int np = 0; np < 2; ++np) {
        const int row = wn * 32 + np * 16 + b_roff;
        b_row[np] = row * 128;
        b_rx[np] = row & 7;
    }

    float acc[2][4][4];
    uint32_t acch[2][4][2];
    #pragma unroll
    for (int i = 0; i < 2; ++i)
        #pragma unroll
        for (int j = 0; j < 4; ++j) {
            #pragma unroll
            for (int q = 0; q < 4; ++q) acc[i][j][q] = 0.0f;
            acch[i][j][0] = 0u; acch[i][j][1] = 0u;
        }

    const int nst = K / KCH;

    // prologue: stages 0..2
    #pragma unroll
    for (int p = 0; p < 3; ++p) {
        if (p < nst) {
            const uint32_t tb = sm + p * STAGE_SZ;
            const long k0 = (long)p * KCH;
            #pragma unroll
            for (int j = 0; j < 2; ++j) {
                if (doA) cpasync16(tb + soff[j], Asrc + k0 + j * 8);
                if (doB) cpasync16(tb + STAGE_B + soff[j], Bsrc + k0 + j * 8);
            }
        }
        CP_COMMIT();
    }

    int stg = 0;
    for (int s = 0; s < nst; ++s) {
        CP_WAIT2();
        __syncthreads();

        const uint32_t tb = sm + stg * STAGE_SZ;
        const uint32_t tba = tb, tbb = tb + STAGE_B;

        #pragma unroll
        for (int ks = 0; ks < NKS; ++ks) {
            const int ca = ks * 2 + a_kh;
            const int cb = ks * 2 + b_kh;

            uint32_t Ahr[2][4], Bhr[2][4];
            #pragma unroll
            for (int mt = 0; mt < 2; ++mt)
                LDSM4(Ahr[mt], tba + a_row[mt] + ((ca ^ a_rx[mt]) << 4));
            #pragma unroll
            for (int np = 0; np < 2; ++np)
                LDSM4(Bhr[np], tbb + b_row[np] + ((cb ^ b_rx[np]) << 4));
            #pragma unroll
            for (int mt = 0; mt < 2; ++mt)
                #pragma unroll
                for (int nt = 0; nt < 4; ++nt) {
                    const int np = nt >> 1, s2 = (nt & 1) * 2;
                    MMAF(acc[mt][nt], Ahr[mt], Bhr[np][s2], Bhr[np][s2 + 1]);
                }

            if (needBlo) {
                uint32_t Blr[2][4];
                #pragma unroll
                for (int np = 0; np < 2; ++np)
                    LDSM4(Blr[np], tbb + b_row[np] + (((cb + 4) ^ b_rx[np]) << 4));
                #pragma unroll
                for (int mt = 0; mt < 2; ++mt)
                    #pragma unroll
                    for (int nt = 0; nt < 4; ++nt) {
                        const int np = nt >> 1, s2 = (nt & 1) * 2;
                        MMAH(acch[mt][nt], Ahr[mt], Blr[np][s2], Blr[np][s2 + 1]);
                    }
            }
        }

        if (s + 3 < nst) {
            int ps = stg + 3; if (ps >= NSTAGE) ps -= NSTAGE;
            const uint32_t pb = sm + ps * STAGE_SZ;
            const long k0 = (long)(s + 3) * KCH;
            #pragma unroll
            for (int j = 0; j < 2; ++j) {
                if (doA) cpasync16(pb + soff[j], Asrc + k0 + j * 8);
                if (doB) cpasync16(pb + STAGE_B + soff[j], Bsrc + k0 + j * 8);
            }
        }
        CP_COMMIT();

        if (++stg == NSTAGE) stg = 0;
    }

    const int r_in = lane >> 2, c_in = (lane & 3) * 2;
    #pragma unroll
    for (int mt = 0; mt < 2; ++mt) {
        #pragma unroll
        for (int half = 0; half < 2; ++half) {
            const long row = row0 + wm * 32 + mt * 16 + half * 8 + r_in;
            #pragma unroll
            for (int nt = 0; nt < 4; ++nt) {
                const int colg = (int)col0 + wn * 32 + nt * 8 + c_in;
                float v0 = acc[mt][nt][half * 2 + 0];
                float v1 = acc[mt][nt][half * 2 + 1];
                if (PMASK) {
                    float2 cf = __half22float2(*reinterpret_cast<__half2*>(&acch[mt][nt][half]));
                    v0 += cf.x;
                    v1 += cf.y;
                }
                v0 *= alpha;
                v1 *= alpha;
                if (mode == 0) {
                    if (bias) { v0 += bias[colg]; v1 += bias[colg + 1]; }
                    *(float2*)((float*)Cv + coff + row * ldc + colg) = make_float2(v0, v1);
                } else if (mode == 1) {
                    uint32_t hw = pack2(__float2half_rn(v0), __float2half_rn(v1));
                    *(uint32_t*)((__half*)Cv + coff + row * ldc + colg) = hw;
                } else {
                    __half* Ch = (__half*)Cv + coff;
                    Ch[(long)colg * ldc + row] = __float2half_rn(v0);
                    Ch[(long)(colg + 1) * ldc + row] = __float2half_rn(v1);
                }
            }
        }
    }
}

// ---------------------------------------------------------------------------
// PV kernel: probs on the fly; 64x256 tile; 4-stage pipeline. (unchanged)
// ---------------------------------------------------------------------------
#define PV_BB   8192
#define PV_STG  40960
#define PV_SMEM (NSTAGE * PV_STG)

__global__ void __launch_bounds__(512, 1)
pv_kernel(const float* __restrict__ S, const __half* __restrict__ V,
          __half* __restrict__ Z)
{
    extern __shared__ char smem[];
    const uint32_t sm = smem_u32(smem);
    const int tid = threadIdx.x, wid = tid >> 5, lane = tid & 31;
    const int z = blockIdx.z;
    const long row0 = (long)blockIdx.y * 64;
    const long col0 = (long)blockIdx.x * 256;

    const int ar  = tid >> 3;
    const int seg = tid & 7;
    const long rowg = row0 + ar;
    const float* Sp = S + (long)z * SSc + rowg * Sq + seg * 4;
    const float m  = g_m [(long)z * Sq + rowg];
    const float ti = g_ti[(long)z * Sq + rowg];
    const uint32_t a_hi = ar * 128 + ((((seg >> 1) + 0) ^ (ar & 7)) << 4) + (seg & 1) * 8;
    const uint32_t a_lo = ar * 128 + ((((seg >> 1) + 4) ^ (ar & 7)) << 4) + (seg & 1) * 8;

    const int br = tid >> 1;
    const int bc = (tid & 1) * 2;
    const __half* Vp = V + (long)z * SDc + (col0 + br) * Sq;
    const uint32_t b_s0 = br * 128 + (((bc + 0) ^ (br & 7)) << 4);
    const uint32_t b_s1 = br * 128 + (((bc + 1) ^ (br & 7)) << 4);
    const int bko = bc * 8;

    const int wm = wid & 3, wn = wid >> 2;
    const int g = lane >> 3, r8 = lane & 7;
    const int a_roff = ((g & 1) << 3) + r8;
    const int a_kh   = g >> 1;
    const int b_roff = ((g >> 1) << 3) + r8;
    const int b_kh   = g & 1;

    const int arc = wm * 16 + a_roff;
    const uint32_t a_rowb = arc * 128;
    const uint32_t a_rx = arc & 7;
    uint32_t b_rowb[4], b_rx[4];
    #pragma unroll
    for (int np = 0; np < 4; ++np) {
        const int row = wn * 64 + np * 16 + b_roff;
        b_rowb[np] = row * 128;
        b_rx[np] = row & 7;
    }

    float acc[8][4];
    uint32_t acch[8][2];
    #pragma unroll
    for (int j = 0; j < 8; ++j) {
        #pragma unroll
        for (int q = 0; q < 4; ++q) acc[j][q] = 0.0f;
        acch[j][0] = 0u; acch[j][1] = 0u;
    }

    const int nst = Sq / 32;

    #pragma unroll
    for (int p = 0; p < 3; ++p) {
        const uint32_t tb = sm + p * PV_STG;
        const long k0 = (long)p * 32;
        cpasync16(tb + PV_BB + b_s0, Vp + k0 + bko);
        cpasync16(tb + PV_BB + b_s1, Vp + k0 + bko + 8);
        CP_COMMIT();
        float4 sv = *(const float4*)(Sp + k0);
        float p0 = __expf(sv.x - m) * ti, p1 = __expf(sv.y - m) * ti;
        float p2 = __expf(sv.z - m) * ti, p3 = __expf(sv.w - m) * ti;
        __half h0, l0, h1, l1, h2, l2, h3, l3;
        split1(p0, h0, l0); split1(p1, h1, l1);
        split1(p2, h2, l2); split1(p3, h3, l3);
        sts8(tb + a_hi, pack2(h0, h1), pack2(h2, h3));
        sts8(tb + a_lo, pack2(l0, l1), pack2(l2, l3));
    }

    int stg = 0;
    #pragma unroll 1
    for (int s = 0; s < nst; ++s) {
        CP_WAIT2();
        __syncthreads();

        const bool pf = (s + 3 < nst);
        int ps = stg + 3; if (ps >= NSTAGE) ps -= NSTAGE;
        const uint32_t pb = sm + ps * PV_STG;
        float4 sv;
        if (pf) {
            const long k2 = (long)(s + 3) * 32;
            cpasync16(pb + PV_BB + b_s0, Vp + k2 + bko);
            cpasync16(pb + PV_BB + b_s1, Vp + k2 + bko + 8);
            sv = *(const float4*)(Sp + k2);
        }

        const uint32_t tb = sm + stg * PV_STG;
        #pragma unroll
        for (int ks = 0; ks < 2; ++ks) {
            const int ca = ks * 2 + a_kh;
            const int cb = ks * 2 + b_kh;
            uint32_t Ah[4], Al[4], Bh[4][4];
            LDSM4(Ah, tb + a_rowb + (((ca + 0) ^ a_rx) << 4));
            LDSM4(Al, tb + a_rowb + (((ca + 4) ^ a_rx) << 4));
            #pragma unroll
            for (int np = 0; np < 4; ++np)
                LDSM4(Bh[np], tb + PV_BB + b_rowb[np] + ((cb ^ b_rx[np]) << 4));
            #pragma unroll
            for (int nt = 0; nt < 8; ++nt) {
                const int np = nt >> 1, s2 = (nt & 1) * 2;
                MMAF(acc[nt], Ah, Bh[np][s2], Bh[np][s2 + 1]);
            }
            #pragma unroll
            for (int nt = 0; nt < 8; ++nt) {
                const int np = nt >> 1, s2 = (nt & 1) * 2;
                MMAH(acch[nt], Al, Bh[np][s2], Bh[np][s2 + 1]);
            }
        }

        if (pf) {
            float p0 = __expf(sv.x - m) * ti, p1 = __expf(sv.y - m) * ti;
            float p2 = __expf(sv.z - m) * ti, p3 = __expf(sv.w - m) * ti;
            __half h0, l0, h1, l1, h2, l2, h3, l3;
            split1(p0, h0, l0); split1(p1, h1, l1);
            split1(p2, h2, l2); split1(p3, h3, l3);
            sts8(pb + a_hi, pack2(h0, h1), pack2(h2, h3));
            sts8(pb + a_lo, pack2(l0, l1), pack2(l2, l3));
        }
        CP_COMMIT();

        if (++stg == NSTAGE) stg = 0;
    }

    const int r_in = lane >> 2, c_in = (lane & 3) * 2;
    __half* Zb = Z + (long)(z / Hq) * Sq * (Hq * Dq) + (long)(z % Hq) * Dq;
    #pragma unroll
    for (int half = 0; half < 2; ++half) {
        const long row = row0 + wm * 16 + half * 8 + r_in;
        #pragma unroll
        for (int nt = 0; nt < 8; ++nt) {
            const int colg = (int)col0 + wn * 64 + nt * 8 + c_in;
            float2 cf = __half22float2(*reinterpret_cast<__half2*>(&acch[nt][half]));
            float v0 = (acc[nt][half * 2 + 0] + cf.x) * (1.0f / 128.0f);
            float v1 = (acc[nt][half * 2 + 1] + cf.y) * (1.0f / 128.0f);
            uint32_t hw = pack2(__float2half_rn(v0), __float2half_rn(v1));
            *(uint32_t*)(Zb + row * (Hq * Dq) + colg) = hw;
        }
    }
}

// ---------------------------------------------------------------------------
__global__ void __launch_bounds__(256) cvt3_kernel(const float* __restrict__ a,
                                                   const float* __restrict__ b,
                                                   const float* __restrict__ c,
                                                   __half* __restrict__ dst)
{
    const float* in = (blockIdx.y == 0) ? a : (blockIdx.y == 1) ? b : c;
    __half* out = dst + (long)blockIdx.y * X_PLANE;
    const long idx = (long)blockIdx.x * 256 + threadIdx.x;
    float4 v = ((const float4*)in)[idx];
    ((uint32_t*)out)[2 * idx]     = pack2(__float2half_rn(v.x), __float2half_rn(v.y));
    ((uint32_t*)out)[2 * idx + 1] = pack2(__float2half_rn(v.z), __float2half_rn(v.w));
}

__global__ void __launch_bounds__(256) tcvt3_kernel(const float* __restrict__ wq,
                                                    const float* __restrict__ wk,
                                                    const float* __restrict__ wv,
                                                    __half* __restrict__ dst)
{
    __shared__ float ts[32][33];
    const int tx = threadIdx.x, ty = threadIdx.y;
    const int mh = blockIdx.z;
    const int mm = mh >> 3, h = mh & 7;
    const float* in = ((mm == 0) ? wq : (mm == 1) ? wk : wv) + (long)h * DDc;
    __half* out = dst + (long)mm * W_PLANE + (long)h * DDc;
    const int r0 = blockIdx.y * 32, c0 = blockIdx.x * 32;
    #pragma unroll
    for (int i = 0; i < 4; ++i)
        ts[ty + 8 * i][tx] = in[(long)(r0 + ty + 8 * i) * Dq + c0 + tx];
    __syncthreads();
    #pragma unroll
    for (int i = 0; i < 4; ++i)
        out[(long)(c0 + ty + 8 * i) * Dq + r0 + tx] =
            __float2half_rn(ts[tx][ty + 8 * i] * 16.0f);
}

__global__ void __launch_bounds__(256) tsplit_wz_kernel(const float* __restrict__ in,
                                                        __half* __restrict__ outh)
{
    __shared__ float ts[32][33];
    const int tx = threadIdx.x, ty = threadIdx.y;
    const int r0 = blockIdx.y * 32, c0 = blockIdx.x * 32;
    const int R = Hq * Dq, C = Dq;
    #pragma unroll
    for (int i = 0; i < 4; ++i)
        ts[ty + 8 * i][tx] = in[(long)(r0 + ty + 8 * i) * C + c0 + tx];
    __syncthreads();
    #pragma unroll
    for (int i = 0; i < 4; ++i) {
        __half h, l;
        split1(ts[tx][ty + 8 * i] * 64.0f, h, l);
        const long o = (long)(c0 + ty + 8 * i) * R + r0 + tx;
        outh[o] = h;
        outh[o + W_PLANE] = l;
    }
}

// ---------------------------------------------------------------------------
__global__ void __launch_bounds__(256) softmax_stats_kernel(float* __restrict__ avg_out)
{
    const int r = blockIdx.x & (Sq - 1);
    const int b = blockIdx.x >> 11;
    const int tid = threadIdx.x;
    __shared__ float sr[8];

    float avg[8];
    #pragma unroll
    for (int i = 0; i < 8; ++i) avg[i] = 0.0f;

    #pragma unroll 1
    for (int h = 0; h < Hq; ++h) {
        const float* p = g_attn + (((long)b * Hq + h) * Sq + r) * Sq;

        float v[8];
        float mx = -1e30f;
        #pragma unroll
        for (int i = 0; i < 8; ++i) { v[i] = p[tid + i * 256]; mx = fmaxf(mx, v[i]); }
        #pragma unroll
        for (int o = 16; o > 0; o >>= 1) mx = fmaxf(mx, __shfl_xor_sync(~0u, mx, o));
        if ((tid & 31) == 0) sr[tid >> 5] = mx;
        __syncthreads();
        float mm = sr[0];
        #pragma unroll
        for (int i = 1; i < 8; ++i) mm = fmaxf(mm, sr[i]);
        __syncthreads();

        float s = 0.f;
        #pragma unroll
        for (int i = 0; i < 8; ++i) { v[i] = __expf(v[i] - mm); s += v[i]; }
        #pragma unroll
        for (int o = 16; o > 0; o >>= 1) s += __shfl_xor_sync(~0u, s, o);
        if ((tid & 31) == 0) sr[tid >> 5] = s;
        __syncthreads();
        float t = 0.f;
        #pragma unroll
        for (int i = 0; i < 8; ++i) t += sr[i];
        __syncthreads();

        const float inv = 1.0f / t;
        #pragma unroll
        for (int i = 0; i < 8; ++i) avg[i] += v[i] * inv;

        if (tid == 0) {
            g_m [((long)b * Hq + h) * Sq + r] = mm;
            g_ti[((long)b * Hq + h) * Sq + r] = 1024.0f / t;
        }
    }

    float* dst = avg_out + ((long)b * Sq + r) * Sq;
    #pragma unroll
    for (int i = 0; i < 8; ++i)
        dst[tid + i * 256] = avg[i] * 0.125f;
}

// ---------------------------------------------------------------------------
extern "C" void kernel_launch(void* const* d_in, const int* in_sizes, int n_in,
                              void* d_out, int out_size)
{
    (void)in_sizes; (void)n_in; (void)out_size;
    const float* Xq = (const float*)d_in[0];
    const float* Xk = (const float*)d_in[1];
    const float* Xv = (const float*)d_in[2];
    const float* Wq = (const float*)d_in[3];
    const float* Wk = (const float*)d_in[4];
    const float* Wv = (const float*)d_in[5];
    const float* Wz = (const float*)d_in[6];
    const float* bz = (const float*)d_in[7];
    float* out = (float*)d_out;
    float* attn_avg = out + (long)Bq * Sq * Dq;

    __half *px, *pw, *pwz, *pqk, *pvt, *pzs;
    float* pattn;
    cudaGetSymbolAddress((void**)&px, g_x);
    cudaGetSymbolAddress((void**)&pw, g_w);
    cudaGetSymbolAddress((void**)&pwz, g_wzt);
    cudaGetSymbolAddress((void**)&pqk, g_qk);
    cudaGetSymbolAddress((void**)&pvt, g_vts);
    cudaGetSymbolAddress((void**)&pzs, g_zs);
    cudaGetSymbolAddress((void**)&pattn, g_attn);

    cudaFuncSetAttribute((const void*)gemm_mma<0, 64>, cudaFuncAttributeMaxDynamicSharedMemorySize, SMEM_SZ);
    cudaFuncSetAttribute((const void*)gemm_mma<1, 32>, cudaFuncAttributeMaxDynamicSharedMemorySize, SMEM_SZ);
    cudaFuncSetAttribute((const void*)pv_kernel, cudaFuncAttributeMaxDynamicSharedMemorySize, PV_SMEM);

    const float inv4 = (float)(1.0 / pow((double)Dq, 0.25));
    const Off noff = { 1, 0, 1, 0 };
    const int ZBIG = 1 << 30;

    // 1) convert inputs + weights
    cvt3_kernel<<<dim3((int)(X_PLANE / 1024), 3), 256>>>(Xq, Xk, Xv, px);
    {
        dim3 tb(32, 8);
        tcvt3_kernel<<<dim3(16, 16, 24), tb>>>(Wq, Wk, Wv, pw);
        tsplit_wz_kernel<<<dim3(16, 128, 1), tb>>>(Wz, pwz);
    }

    // 2) Q+K+V projections in ONE launch (z 0..31 = QK mode 1; z 32..47 = V mode 2)
    {
        dim3 grid(Dq / 128, Sq / 128, 48);
        Off oa = { 8, SDc, 1, 0 };
        Off ob = { 16, W_PLANE, 8, DDc };
        Off oc = { 16, QK_PLANE, 16, SDc };
        Off ocv = { 1, SDc, 1, 0 };
        gemm_mma<0, 64><<<grid, GTHREADS, SMEM_SZ>>>(px, 0, pw, 0, pqk,
                                                     Dq, Dq, Dq, Dq, oa, ob, oc,
                                                     inv4 * 0.25f, nullptr, 1,
                                                     32, pvt, Sq, 0.25f, ocv);
    }

    // 3) scores (fp32) = q_s.k_s / 16
    {
        dim3 grid(Sq / 128, Sq / 128, Bq * Hq);
        Off oa = { 1, SDc, 1, 0 };
        Off ob = { 1, SDc, 1, 0 };
        Off oc = { 1, SSc, 1, 0 };
        gemm_mma<0, 64><<<grid, GTHREADS, SMEM_SZ>>>(pqk, 0, pqk + QK_PLANE, 0, pattn,
                                                     Dq, Dq, Dq, Sq, oa, ob, oc,
                                                     1.0f / 16.0f, nullptr, 0,
                                                     ZBIG, nullptr, 0, 0.0f, noff);
    }

    // 4) streaming softmax stats + head-average
    softmax_stats_kernel<<<Bq * Sq, 256>>>(attn_avg);

    // 5) PV with on-the-fly softmax probs
    pv_kernel<<<dim3(2, 32, Bq * Hq), 512, PV_SMEM>>>(pattn, pvt, pzs);

    // 6) out = (z_s . wz_s)/2048 + bz
    {
        dim3 grid(Dq / 128, (Bq * Sq) / 128, 1);
        gemm_mma<1, 32><<<grid, GTHREADS, SMEM_SZ>>>(pzs, 0, pwz, W_PLANE, out,
                                                     Hq * Dq, Hq * Dq, Hq * Dq, Dq,
                                                     noff, noff, noff, 1.0f / 2048.0f, bz, 0,
                                                     ZBIG, nullptr, 0, 0.0f, noff);
    }
}